// round 3
// baseline (speedup 1.0000x reference)
#include <cuda_runtime.h>
#include <cstdint>

// ---------------- problem constants ----------------
#define B_    8
#define T_    2048
#define DIM_  1024
#define E_    2048
#define M_TOT (B_ * T_)   // 16384 rows for all GEMMs

// ---------------- scratch (no allocs allowed) ----------------
static __device__ float g_xproj[(size_t)M_TOT * E_];
static __device__ float g_u[(size_t)M_TOT * E_];
static __device__ float g_outs[(size_t)M_TOT * E_];
static __device__ float g_x   [(size_t)M_TOT * DIM_];   // rna-rounded copies
static __device__ float g_win [(size_t)E_ * DIM_];
static __device__ float g_wx  [(size_t)E_ * E_];
static __device__ float g_wout[(size_t)DIM_ * E_];

// ---------------- helpers ----------------
__device__ __forceinline__ uint32_t smem_to_u32(const void* p) {
    uint32_t a;
    asm("{ .reg .u64 t; cvta.to.shared.u64 t, %1; cvt.u32.u64 %0, t; }" : "=r"(a) : "l"(p));
    return a;
}

__device__ __forceinline__ float rna1(float x) {
    uint32_t u;
    asm("cvt.rna.tf32.f32 %0, %1;" : "=r"(u) : "f"(x));
    return __uint_as_float(u);
}
__device__ __forceinline__ float4 rna4(float4 v) {
    return make_float4(rna1(v.x), rna1(v.y), rna1(v.z), rna1(v.w));
}

__device__ __forceinline__ void cp16(void* s, const void* g) {
    asm volatile("cp.async.cg.shared.global [%0], [%1], 16;"
                 :: "r"(smem_to_u32(s)), "l"(g) : "memory");
}
#define CP_COMMIT() asm volatile("cp.async.commit_group;" ::: "memory")
#define CP_WAIT1()  asm volatile("cp.async.wait_group 1;" ::: "memory")

// tf32 mma: D(16x8) += A(16x8) * B(8x8), row.col, fp32 accum
__device__ __forceinline__ void mma_tf32(float* c, const uint32_t* a, const uint32_t* b) {
    asm volatile(
        "mma.sync.aligned.m16n8k8.row.col.f32.tf32.tf32.f32 "
        "{%0,%1,%2,%3}, {%4,%5,%6,%7}, {%8,%9}, {%0,%1,%2,%3};"
        : "+f"(c[0]), "+f"(c[1]), "+f"(c[2]), "+f"(c[3])
        : "r"(a[0]), "r"(a[1]), "r"(a[2]), "r"(a[3]), "r"(b[0]), "r"(b[1]));
}

// ---------------- GEMM config ----------------
#define BM 128
#define BN 128
#define BK 32
#define SROW 36                       // padded row stride (floats), 144B (16B multiple)
#define STAGE_FLOATS (2 * BM * SROW)  // A tile then B tile
#define STAGES 3
#define SMEM_BYTES (STAGES * STAGE_FLOATS * 4)

// C[m,n] = sum_k A[m,k] * Bw[n,k]; mode 0: silu+rna, 1: +bias, 2: identity
__global__ void __launch_bounds__(128, 2)
gemm_tf32(const float* __restrict__ A, const float* __restrict__ Bw,
          const float* __restrict__ bias, float* __restrict__ C,
          int Ktot, int Ntot, int mode)
{
    extern __shared__ __align__(16) float smem[];

    const int tid  = threadIdx.x;
    const int wid  = tid >> 5;
    const int lane = tid & 31;
    const int m0 = blockIdx.y * BM;
    const int n0 = blockIdx.x * BN;
    const int KT = Ktot / BK;

    // cp.async thread map: 16B chunks; 8 chunks per 128B row
    const int lr = tid >> 3;          // 0..15
    const int lc = (tid & 7) * 4;     // float col 0,4,...,28

    auto load_stage = [&](int kt, int buf) {
        float* sA = smem + buf * STAGE_FLOATS;
        float* sB = sA + BM * SROW;
        const int k0 = kt * BK;
#pragma unroll
        for (int p = 0; p < 8; ++p) {
            const int row = p * 16 + lr;
            cp16(&sA[row * SROW + lc], &A [(size_t)(m0 + row) * Ktot + k0 + lc]);
            cp16(&sB[row * SROW + lc], &Bw[(size_t)(n0 + row) * Ktot + k0 + lc]);
        }
    };

    // warp grid 2x2, warp tile 64x64
    const int wm = (wid >> 1) * 64;
    const int wn = (wid & 1) * 64;
    const int qr = lane >> 2;         // 0..7
    const int qc = lane & 3;          // 0..3

    float acc[4][8][4];
#pragma unroll
    for (int mt = 0; mt < 4; ++mt)
#pragma unroll
        for (int nt = 0; nt < 8; ++nt)
#pragma unroll
            for (int i = 0; i < 4; ++i) acc[mt][nt][i] = 0.0f;

    auto compute = [&](int buf) {
        const float* sA = smem + buf * STAGE_FLOATS;
        const float* sB = sA + BM * SROW;
#pragma unroll
        for (int ks = 0; ks < 4; ++ks) {
            const int k0 = ks * 8;
            uint32_t af[4][4];
#pragma unroll
            for (int mt = 0; mt < 4; ++mt) {
                const int base = (wm + mt * 16 + qr) * SROW + k0 + qc;
                af[mt][0] = __float_as_uint(sA[base]);
                af[mt][1] = __float_as_uint(sA[base + 8 * SROW]);
                af[mt][2] = __float_as_uint(sA[base + 4]);
                af[mt][3] = __float_as_uint(sA[base + 8 * SROW + 4]);
            }
            uint32_t bf[8][2];
#pragma unroll
            for (int nt = 0; nt < 8; ++nt) {
                const int base = (wn + nt * 8 + qr) * SROW + k0 + qc;
                bf[nt][0] = __float_as_uint(sB[base]);
                bf[nt][1] = __float_as_uint(sB[base + 4]);
            }
#pragma unroll
            for (int mt = 0; mt < 4; ++mt)
#pragma unroll
                for (int nt = 0; nt < 8; ++nt)
                    mma_tf32(acc[mt][nt], af[mt], bf[nt]);
        }
    };

    // ---- pipelined mainloop ----
    load_stage(0, 0); CP_COMMIT();
    load_stage(1, 1); CP_COMMIT();
#pragma unroll 1
    for (int kt = 0; kt < KT; ++kt) {
        CP_WAIT1();
        __syncthreads();
        const int nk = kt + 2;
        if (nk < KT) load_stage(nk, nk % STAGES);
        CP_COMMIT();
        compute(kt % STAGES);
    }

    // ---- epilogue ----
#pragma unroll
    for (int mt = 0; mt < 4; ++mt) {
        const int row0 = m0 + wm + mt * 16 + qr;
#pragma unroll
        for (int nt = 0; nt < 8; ++nt) {
            const int col0 = n0 + wn + nt * 8 + 2 * qc;
            float v0 = acc[mt][nt][0], v1 = acc[mt][nt][1];
            float v2 = acc[mt][nt][2], v3 = acc[mt][nt][3];
            if (mode == 0) {
                v0 = rna1(v0 * __fdividef(1.0f, 1.0f + __expf(-v0)));
                v1 = rna1(v1 * __fdividef(1.0f, 1.0f + __expf(-v1)));
                v2 = rna1(v2 * __fdividef(1.0f, 1.0f + __expf(-v2)));
                v3 = rna1(v3 * __fdividef(1.0f, 1.0f + __expf(-v3)));
            } else if (mode == 1) {
                const float b0 = bias[col0], b1 = bias[col0 + 1];
                v0 += b0; v1 += b1; v2 += b0; v3 += b1;
            }
            *reinterpret_cast<float2*>(&C[(size_t)row0 * Ntot + col0])       = make_float2(v0, v1);
            *reinterpret_cast<float2*>(&C[(size_t)(row0 + 8) * Ntot + col0]) = make_float2(v2, v3);
        }
    }
}

// ---------------- rna copy (pre-round MMA operands once) ----------------
__global__ void __launch_bounds__(256)
rna_copy(const float* __restrict__ src, float* __restrict__ dst, int n4)
{
    const int i = blockIdx.x * blockDim.x + threadIdx.x;
    if (i < n4)
        reinterpret_cast<float4*>(dst)[i] = rna4(reinterpret_cast<const float4*>(src)[i]);
}

// ---------------- sequential scan: h = tanh(u + d*h); out = h * silu(h) ----------------
__global__ void __launch_bounds__(128)
scan_kernel(const float* __restrict__ U, const float* __restrict__ h0,
            const float* __restrict__ dvec, float* __restrict__ outs,
            float* __restrict__ hfin)
{
    const int id = blockIdx.x * blockDim.x + threadIdx.x;   // 0 .. B*E-1
    const int b = id / E_;
    const int e = id - b * E_;
    const float dc = fminf(fmaxf(dvec[e], -0.99f), 0.99f);
    float h = h0[id];
    const size_t base = (size_t)b * T_ * E_ + e;
#pragma unroll 4
    for (int t = 0; t < T_; ++t) {
        const float uv = U[base + (size_t)t * E_];
        const float a  = fmaf(dc, h, uv);
        const float e2 = __expf(-2.0f * a);
        h = __fdividef(1.0f - e2, 1.0f + e2);               // tanh(a)
        const float sg = __fdividef(1.0f, 1.0f + __expf(-h));
        outs[base + (size_t)t * E_] = rna1(h * h * sg);     // h * silu(h), tf32-rounded
    }
    hfin[id] = h;
}

// ---------------- launcher ----------------
extern "C" void kernel_launch(void* const* d_in, const int* in_sizes, int n_in,
                              void* d_out, int out_size)
{
    const float* x     = (const float*)d_in[0];
    const float* h0    = (const float*)d_in[1];
    const float* W_in  = (const float*)d_in[2];
    const float* W_x   = (const float*)d_in[3];
    const float* dvec  = (const float*)d_in[4];
    const float* bias  = (const float*)d_in[5];
    const float* W_out = (const float*)d_in[6];
    float* out = (float*)d_out;

    float *xproj, *u, *outs, *xr, *win, *wx, *wout;
    cudaGetSymbolAddress((void**)&xproj, g_xproj);
    cudaGetSymbolAddress((void**)&u,     g_u);
    cudaGetSymbolAddress((void**)&outs,  g_outs);
    cudaGetSymbolAddress((void**)&xr,    g_x);
    cudaGetSymbolAddress((void**)&win,   g_win);
    cudaGetSymbolAddress((void**)&wx,    g_wx);
    cudaGetSymbolAddress((void**)&wout,  g_wout);

    cudaFuncSetAttribute(gemm_tf32, cudaFuncAttributeMaxDynamicSharedMemorySize, SMEM_BYTES);

    // pre-round all MMA operands to tf32 (rna) once
    {
        int n4;
        n4 = (M_TOT * DIM_) / 4; rna_copy<<<(n4 + 255) / 256, 256>>>(x, xr, n4);
        n4 = (E_ * DIM_) / 4;    rna_copy<<<(n4 + 255) / 256, 256>>>(W_in, win, n4);
        n4 = (E_ * E_) / 4;      rna_copy<<<(n4 + 255) / 256, 256>>>(W_x, wx, n4);
        n4 = (DIM_ * E_) / 4;    rna_copy<<<(n4 + 255) / 256, 256>>>(W_out, wout, n4);
    }

    // GEMM1: x[16384,1024] @ W_in[2048,1024]^T -> silu -> xproj (tf32-rounded at store)
    gemm_tf32<<<dim3(E_ / BN, M_TOT / BM), 128, SMEM_BYTES>>>(xr, win, nullptr, xproj, DIM_, E_, 0);
    // GEMM2: xproj @ W_x[2048,2048]^T + b -> u (fp32)
    gemm_tf32<<<dim3(E_ / BN, M_TOT / BM), 128, SMEM_BYTES>>>(xproj, wx, bias, u, E_, E_, 1);
    // scan over T; outs tf32-rounded; h_final appended after output
    scan_kernel<<<(B_ * E_) / 128, 128>>>(u, h0, dvec, outs, out + (size_t)M_TOT * DIM_);
    // GEMM3: outs @ W_out[1024,2048]^T -> output[16384,1024]
    gemm_tf32<<<dim3(DIM_ / BN, M_TOT / BM), 128, SMEM_BYTES>>>(outs, wout, nullptr, out, E_, DIM_, 2);
}

// round 5
// speedup vs baseline: 1.6279x; 1.6279x over previous
#include <cuda_runtime.h>
#include <cuda_fp16.h>
#include <cstdint>

// ---------------- problem constants ----------------
#define B_    8
#define T_    2048
#define DIM_  1024
#define E_    2048
#define M_TOT (B_ * T_)   // 16384 rows for all GEMMs

// ---------------- scratch (no allocs allowed) ----------------
static __device__ __half g_xh   [(size_t)M_TOT * DIM_];  // half copies of MMA operands
static __device__ __half g_winh [(size_t)E_ * DIM_];
static __device__ __half g_wxh  [(size_t)E_ * E_];
static __device__ __half g_wouth[(size_t)DIM_ * E_];
static __device__ __half g_xproj[(size_t)M_TOT * E_];    // GEMM1 out (half)
static __device__ float  g_u    [(size_t)M_TOT * E_];    // GEMM2 out (fp32, scan input)
static __device__ __half g_outs [(size_t)M_TOT * E_];    // scan out (half, GEMM3 input)

// ---------------- helpers ----------------
__device__ __forceinline__ uint32_t smem_to_u32(const void* p) {
    uint32_t a;
    asm("{ .reg .u64 t; cvta.to.shared.u64 t, %1; cvt.u32.u64 %0, t; }" : "=r"(a) : "l"(p));
    return a;
}

__device__ __forceinline__ void cp16(void* s, const void* g) {
    asm volatile("cp.async.cg.shared.global [%0], [%1], 16;"
                 :: "r"(smem_to_u32(s)), "l"(g) : "memory");
}
#define CP_COMMIT() asm volatile("cp.async.commit_group;" ::: "memory")
#define CP_WAIT1()  asm volatile("cp.async.wait_group 1;" ::: "memory")

// fp16 mma: D(16x8,f32) += A(16x16,f16) * B(16x8,f16)
__device__ __forceinline__ void mma_f16(float* c, const uint32_t* a, const uint32_t* b) {
    asm volatile(
        "mma.sync.aligned.m16n8k16.row.col.f32.f16.f16.f32 "
        "{%0,%1,%2,%3}, {%4,%5,%6,%7}, {%8,%9}, {%0,%1,%2,%3};"
        : "+f"(c[0]), "+f"(c[1]), "+f"(c[2]), "+f"(c[3])
        : "r"(a[0]), "r"(a[1]), "r"(a[2]), "r"(a[3]), "r"(b[0]), "r"(b[1]));
}

// ---------------- GEMM config ----------------
#define BM 128
#define BN 128
#define BK 64
#define SROW 72                         // padded row stride in halves (144B, 16B mult.)
#define TILE_HALVES (BM * SROW)         // one operand tile
#define STAGE_HALVES (2 * TILE_HALVES)  // A tile then B tile
#define STAGES 3
#define SMEM_BYTES (STAGES * STAGE_HALVES * 2)

// C[m,n] = sum_k A[m,k] * Bw[n,k]
// MODE 0: silu -> half C.  MODE 1: +bias -> float C.  MODE 2: identity -> float C.
template<int MODE>
__global__ void __launch_bounds__(128, 2)
gemm_fp16(const __half* __restrict__ A, const __half* __restrict__ Bw,
          const float* __restrict__ bias, void* __restrict__ Cout,
          int Ktot, int Ntot)
{
    extern __shared__ __align__(16) __half smem[];

    const int tid  = threadIdx.x;
    const int wid  = tid >> 5;
    const int lane = tid & 31;
    const int m0 = blockIdx.y * BM;
    const int n0 = blockIdx.x * BN;
    const int KT = Ktot / BK;

    // cp.async thread map: 16B (8-half) chunks; 8 chunks per 128B row
    const int lr = tid >> 3;          // 0..15
    const int lc = (tid & 7) * 8;     // half col 0,8,...,56

    auto load_stage = [&](int kt, int buf) {
        __half* sA = smem + buf * STAGE_HALVES;
        __half* sB = sA + TILE_HALVES;
        const int k0 = kt * BK;
#pragma unroll
        for (int p = 0; p < 8; ++p) {
            const int row = p * 16 + lr;
            cp16(&sA[row * SROW + lc], &A [(size_t)(m0 + row) * Ktot + k0 + lc]);
            cp16(&sB[row * SROW + lc], &Bw[(size_t)(n0 + row) * Ktot + k0 + lc]);
        }
    };

    // warp grid 2x2, warp tile 64x64
    const int wm = (wid >> 1) * 64;
    const int wn = (wid & 1) * 64;
    const int qr = lane >> 2;         // 0..7
    const int qc = lane & 3;          // 0..3

    float acc[4][8][4];
#pragma unroll
    for (int mt = 0; mt < 4; ++mt)
#pragma unroll
        for (int nt = 0; nt < 8; ++nt)
#pragma unroll
            for (int i = 0; i < 4; ++i) acc[mt][nt][i] = 0.0f;

    auto compute = [&](int buf) {
        const __half* sA = smem + buf * STAGE_HALVES;
        const __half* sB = sA + TILE_HALVES;
#pragma unroll
        for (int ks = 0; ks < 4; ++ks) {          // 4 steps of k=16
            const int k0 = ks * 16;
            uint32_t af[4][4];
#pragma unroll
            for (int mt = 0; mt < 4; ++mt) {
                const int base = (wm + mt * 16 + qr) * SROW + k0 + qc * 2;
                af[mt][0] = *reinterpret_cast<const uint32_t*>(&sA[base]);
                af[mt][1] = *reinterpret_cast<const uint32_t*>(&sA[base + 8 * SROW]);
                af[mt][2] = *reinterpret_cast<const uint32_t*>(&sA[base + 8]);
                af[mt][3] = *reinterpret_cast<const uint32_t*>(&sA[base + 8 * SROW + 8]);
            }
            uint32_t bf[8][2];
#pragma unroll
            for (int nt = 0; nt < 8; ++nt) {
                const int base = (wn + nt * 8 + qr) * SROW + k0 + qc * 2;
                bf[nt][0] = *reinterpret_cast<const uint32_t*>(&sB[base]);
                bf[nt][1] = *reinterpret_cast<const uint32_t*>(&sB[base + 8]);
            }
#pragma unroll
            for (int mt = 0; mt < 4; ++mt)
#pragma unroll
                for (int nt = 0; nt < 8; ++nt)
                    mma_f16(acc[mt][nt], af[mt], bf[nt]);
        }
    };

    // ---- pipelined mainloop (3-stage cp.async) ----
    load_stage(0, 0); CP_COMMIT();
    load_stage(1, 1); CP_COMMIT();
#pragma unroll 1
    for (int kt = 0; kt < KT; ++kt) {
        CP_WAIT1();
        __syncthreads();
        const int nk = kt + 2;
        if (nk < KT) load_stage(nk, nk % STAGES);
        CP_COMMIT();
        compute(kt % STAGES);
    }

    // ---- epilogue ----
#pragma unroll
    for (int mt = 0; mt < 4; ++mt) {
        const int row0 = m0 + wm + mt * 16 + qr;
#pragma unroll
        for (int nt = 0; nt < 8; ++nt) {
            const int col0 = n0 + wn + nt * 8 + 2 * qc;
            float v0 = acc[mt][nt][0], v1 = acc[mt][nt][1];
            float v2 = acc[mt][nt][2], v3 = acc[mt][nt][3];
            if (MODE == 0) {
                // silu, store half
                v0 = v0 * __fdividef(1.0f, 1.0f + __expf(-v0));
                v1 = v1 * __fdividef(1.0f, 1.0f + __expf(-v1));
                v2 = v2 * __fdividef(1.0f, 1.0f + __expf(-v2));
                v3 = v3 * __fdividef(1.0f, 1.0f + __expf(-v3));
                __half* C = (__half*)Cout;
                *reinterpret_cast<__half2*>(&C[(size_t)row0 * Ntot + col0]) =
                    __halves2half2(__float2half_rn(v0), __float2half_rn(v1));
                *reinterpret_cast<__half2*>(&C[(size_t)(row0 + 8) * Ntot + col0]) =
                    __halves2half2(__float2half_rn(v2), __float2half_rn(v3));
            } else {
                if (MODE == 1) {
                    const float b0 = bias[col0], b1 = bias[col0 + 1];
                    v0 += b0; v1 += b1; v2 += b0; v3 += b1;
                }
                float* C = (float*)Cout;
                *reinterpret_cast<float2*>(&C[(size_t)row0 * Ntot + col0])       = make_float2(v0, v1);
                *reinterpret_cast<float2*>(&C[(size_t)(row0 + 8) * Ntot + col0]) = make_float2(v2, v3);
            }
        }
    }
}

// ---------------- float -> half convert ----------------
__global__ void __launch_bounds__(256)
f2h_copy(const float* __restrict__ src, __half* __restrict__ dst, int n4)
{
    const int i = blockIdx.x * blockDim.x + threadIdx.x;
    if (i < n4) {
        float4 v = reinterpret_cast<const float4*>(src)[i];
        __half2 h0 = __floats2half2_rn(v.x, v.y);
        __half2 h1 = __floats2half2_rn(v.z, v.w);
        uint2 pk;
        pk.x = *reinterpret_cast<uint32_t*>(&h0);
        pk.y = *reinterpret_cast<uint32_t*>(&h1);
        *reinterpret_cast<uint2*>(&dst[(size_t)i * 4]) = pk;
    }
}

// ---------------- sequential scan: h = tanh(u + d*h); out = h * silu(h) ----------------
// tanh chain folded: e2 = 2^(c1*h + c0_t), c1 = -2*d*log2e (const), c0_t = -2*log2e*u_t
// h = 2/(1+e2) - 1.  Chain: FFMA -> ex2 -> FADD -> rcp -> FFMA  (~44 cyc/step)
__global__ void __launch_bounds__(128)
scan_kernel(const float* __restrict__ U, const float* __restrict__ h0,
            const float* __restrict__ dvec, __half* __restrict__ outs,
            float* __restrict__ hfin)
{
    const int id = blockIdx.x * blockDim.x + threadIdx.x;   // 0 .. B*E-1
    const int b = id / E_;
    const int e = id - b * E_;
    const float LOG2E = 1.4426950408889634f;
    const float dc = fminf(fmaxf(dvec[e], -0.99f), 0.99f);
    const float c1 = -2.0f * LOG2E * dc;
    float h = h0[id];
    const size_t base = (size_t)b * T_ * E_ + e;
#pragma unroll 4
    for (int t = 0; t < T_; ++t) {
        const float uv = U[base + (size_t)t * E_];
        const float c0 = -2.0f * LOG2E * uv;      // off the critical path
        float e2, r;
        asm("ex2.approx.f32 %0, %1;" : "=f"(e2) : "f"(fmaf(c1, h, c0)));
        asm("rcp.approx.f32 %0, %1;" : "=f"(r) : "f"(1.0f + e2));
        h = fmaf(2.0f, r, -1.0f);                 // tanh(u + d*h)
        // out = h * silu(h) = h^2 * sigmoid(h)  (off the critical path)
        float eh, sr;
        asm("ex2.approx.f32 %0, %1;" : "=f"(eh) : "f"(-LOG2E * h));
        asm("rcp.approx.f32 %0, %1;" : "=f"(sr) : "f"(1.0f + eh));
        outs[base + (size_t)t * E_] = __float2half_rn(h * h * sr);
    }
    hfin[id] = h;
}

// ---------------- launcher ----------------
extern "C" void kernel_launch(void* const* d_in, const int* in_sizes, int n_in,
                              void* d_out, int out_size)
{
    const float* x     = (const float*)d_in[0];
    const float* h0    = (const float*)d_in[1];
    const float* W_in  = (const float*)d_in[2];
    const float* W_x   = (const float*)d_in[3];
    const float* dvec  = (const float*)d_in[4];
    const float* bias  = (const float*)d_in[5];
    const float* W_out = (const float*)d_in[6];
    float* out = (float*)d_out;

    __half *xh, *winh, *wxh, *wouth, *xproj, *outs;
    float *u;
    cudaGetSymbolAddress((void**)&xh,    g_xh);
    cudaGetSymbolAddress((void**)&winh,  g_winh);
    cudaGetSymbolAddress((void**)&wxh,   g_wxh);
    cudaGetSymbolAddress((void**)&wouth, g_wouth);
    cudaGetSymbolAddress((void**)&xproj, g_xproj);
    cudaGetSymbolAddress((void**)&u,     g_u);
    cudaGetSymbolAddress((void**)&outs,  g_outs);

    cudaFuncSetAttribute(gemm_fp16<0>, cudaFuncAttributeMaxDynamicSharedMemorySize, SMEM_BYTES);
    cudaFuncSetAttribute(gemm_fp16<1>, cudaFuncAttributeMaxDynamicSharedMemorySize, SMEM_BYTES);
    cudaFuncSetAttribute(gemm_fp16<2>, cudaFuncAttributeMaxDynamicSharedMemorySize, SMEM_BYTES);

    // convert MMA operands to half once
    {
        int n4;
        n4 = (M_TOT * DIM_) / 4; f2h_copy<<<(n4 + 255) / 256, 256>>>(x, xh, n4);
        n4 = (E_ * DIM_) / 4;    f2h_copy<<<(n4 + 255) / 256, 256>>>(W_in, winh, n4);
        n4 = (E_ * E_) / 4;      f2h_copy<<<(n4 + 255) / 256, 256>>>(W_x, wxh, n4);
        n4 = (DIM_ * E_) / 4;    f2h_copy<<<(n4 + 255) / 256, 256>>>(W_out, wouth, n4);
    }

    // GEMM1: x @ W_in^T -> silu -> xproj (half)
    gemm_fp16<0><<<dim3(E_ / BN, M_TOT / BM), 128, SMEM_BYTES>>>(xh, winh, nullptr, xproj, DIM_, E_);
    // GEMM2: xproj @ W_x^T + b -> u (fp32)
    gemm_fp16<1><<<dim3(E_ / BN, M_TOT / BM), 128, SMEM_BYTES>>>(xproj, wxh, bias, u, E_, E_);
    // scan over T; outs half; h_final appended after output
    scan_kernel<<<(B_ * E_) / 128, 128>>>(u, h0, dvec, outs, out + (size_t)M_TOT * DIM_);
    // GEMM3: outs @ W_out^T -> output (fp32)
    gemm_fp16<2><<<dim3(DIM_ / BN, M_TOT / BM), 128, SMEM_BYTES>>>(outs, wouth, nullptr, out, E_, DIM_);
}